// round 5
// baseline (speedup 1.0000x reference)
#include <cuda_runtime.h>

typedef unsigned long long u64;

#define CB  2048
#define CT  512
#define CI  64
#define CH  32
#define CG  128

// Scratch: g_xg[((t*CB + b)*32 + j)*2 + {0,1}] = {(xg_i,xg_f),(xg_g,xg_o)} for unit j.
// One extra timestep slab so K2's t+1 prefetch never reads OOB.
__device__ u64 g_xg[(size_t)(CT + 1) * CB * 64];

__device__ __forceinline__ u64 ffma2(u64 a, u64 b, u64 c) {
    u64 d;
    asm("fma.rn.f32x2 %0, %1, %2, %3;" : "=l"(d) : "l"(a), "l"(b), "l"(c));
    return d;
}
__device__ __forceinline__ u64 pack2(float lo, float hi) {
    u64 d;
    asm("mov.b64 %0, {%1, %2};" : "=l"(d) : "f"(lo), "f"(hi));
    return d;
}
__device__ __forceinline__ float2 unpack2(u64 v) {
    float2 r;
    asm("mov.b64 {%0, %1}, %2;" : "=f"(r.x), "=f"(r.y) : "l"(v));
    return r;
}

// ---------------------------------------------------------------------------
// K1: input projection as ONE flattened GEMM over rows m = b*CT + t.
//   out_row(m) = x_row(m) @ W_ih^T + bias      [1M x 64] x [64 x 128]
// Block: 256 thr, 8 tiles of 128 rows (1024 consecutive rows), W staged once,
// x double-buffered in smem (coalesced float4 loads, transpose via STS).
// Thread tile: 2 j-cols x 4 gate-blocks x 8 rows (f32x2 over row pairs).
// ---------------------------------------------------------------------------
#define WTS2 130      // u64 stride for Wt2 rows
#define XTS  132      // float stride for xs rows (k index)
#define K1T  8        // row-tiles per block

extern __shared__ char sm1[];

__global__ __launch_bounds__(256, 1) void k1_inproj(
    const float* __restrict__ x, const float* __restrict__ Wih,
    const float* __restrict__ bih, const float* __restrict__ bhh)
{
    u64*   Wt2 = (u64*)sm1;                        // Wt2[k*WTS2 + g] = {w,w}
    float* xs0 = (float*)(sm1 + 64 * WTS2 * 8);    // xs[k*XTS + r]
    float* xs1 = xs0 + 64 * XTS;
    const int tid = threadIdx.x;
    const size_t m0 = (size_t)blockIdx.x * (128 * K1T);

    // Stage W_ih duplicated (once per block)
    #pragma unroll
    for (int idx = tid; idx < CG * CI; idx += 256) {
        int g = idx >> 6, k = idx & 63;
        float w = Wih[idx];
        Wt2[k * WTS2 + g] = pack2(w, w);
    }

    const int tx = tid & 15, ty = tid >> 4;
    const int jj0 = tx * 2, r0 = ty * 8;
    const int mr = tid >> 4, kq = tid & 15;   // staging coords (row, float4-col)

    // Bias pairs
    u64 bd[2][4];
    #pragma unroll
    for (int q = 0; q < 2; q++)
        #pragma unroll
        for (int gb = 0; gb < 4; gb++) {
            int g = gb * 32 + jj0 + q;
            float bs = bih[g] + bhh[g];
            bd[q][gb] = pack2(bs, bs);
        }

    const float4* x4 = (const float4*)x;   // 16 float4 per row

    // Prologue: load + stage tile 0 into xs0
    float4 nxt[8];
    #pragma unroll
    for (int i = 0; i < 8; i++)
        nxt[i] = x4[(m0 + mr + i * 16) * 16 + kq];
    #pragma unroll
    for (int i = 0; i < 8; i++) {
        float* d = &xs0[(4 * kq) * XTS + mr + i * 16];
        d[0 * XTS] = nxt[i].x;  d[1 * XTS] = nxt[i].y;
        d[2 * XTS] = nxt[i].z;  d[3 * XTS] = nxt[i].w;
    }
    __syncthreads();

    for (int tile = 0; tile < K1T; tile++) {
        float* cur = (tile & 1) ? xs1 : xs0;
        float* alt = (tile & 1) ? xs0 : xs1;
        const size_t mt = m0 + (size_t)tile * 128;

        // Prefetch next tile's x into registers (hidden under the k-loop)
        if (tile + 1 < K1T) {
            #pragma unroll
            for (int i = 0; i < 8; i++)
                nxt[i] = x4[(mt + 128 + mr + i * 16) * 16 + kq];
        }

        u64 acc[2][4][4];
        #pragma unroll
        for (int q = 0; q < 2; q++)
            #pragma unroll
            for (int gb = 0; gb < 4; gb++)
                #pragma unroll
                for (int p = 0; p < 4; p++) acc[q][gb][p] = bd[q][gb];

        #pragma unroll 4
        for (int k = 0; k < CI; k++) {
            const ulonglong2 xa = *(const ulonglong2*)&cur[k * XTS + r0];
            const ulonglong2 xb = *(const ulonglong2*)&cur[k * XTS + r0 + 4];
            u64 xp[4] = {xa.x, xa.y, xb.x, xb.y};
            const ulonglong2 w0 = *(const ulonglong2*)&Wt2[k * WTS2 +  0 + jj0];
            const ulonglong2 w1 = *(const ulonglong2*)&Wt2[k * WTS2 + 32 + jj0];
            const ulonglong2 w2 = *(const ulonglong2*)&Wt2[k * WTS2 + 64 + jj0];
            const ulonglong2 w3 = *(const ulonglong2*)&Wt2[k * WTS2 + 96 + jj0];
            #pragma unroll
            for (int p = 0; p < 4; p++) {
                acc[0][0][p] = ffma2(xp[p], w0.x, acc[0][0][p]);
                acc[0][1][p] = ffma2(xp[p], w1.x, acc[0][1][p]);
                acc[0][2][p] = ffma2(xp[p], w2.x, acc[0][2][p]);
                acc[0][3][p] = ffma2(xp[p], w3.x, acc[0][3][p]);
                acc[1][0][p] = ffma2(xp[p], w0.y, acc[1][0][p]);
                acc[1][1][p] = ffma2(xp[p], w1.y, acc[1][1][p]);
                acc[1][2][p] = ffma2(xp[p], w2.y, acc[1][2][p]);
                acc[1][3][p] = ffma2(xp[p], w3.y, acc[1][3][p]);
            }
        }

        // Stage next tile into alt buffer
        if (tile + 1 < K1T) {
            #pragma unroll
            for (int i = 0; i < 8; i++) {
                float* d = &alt[(4 * kq) * XTS + mr + i * 16];
                d[0 * XTS] = nxt[i].x;  d[1 * XTS] = nxt[i].y;
                d[2 * XTS] = nxt[i].z;  d[3 * XTS] = nxt[i].w;
            }
        }

        // Store results. Row pair (even m_e, odd m_e+1) = consecutive t, same b.
        #pragma unroll
        for (int p = 0; p < 4; p++) {
            const size_t m_e = mt + r0 + 2 * p;
            const int b = (int)(m_e >> 9);
            const int t = (int)(m_e & 511);
            #pragma unroll
            for (int q = 0; q < 2; q++) {
                float2 g0 = unpack2(acc[q][0][p]);
                float2 g1 = unpack2(acc[q][1][p]);
                float2 g2 = unpack2(acc[q][2][p]);
                float2 g3 = unpack2(acc[q][3][p]);
                u64* dst = g_xg + ((size_t)t * CB + b) * 64 + (jj0 + q) * 2;
                ulonglong2 ve, vo;
                ve.x = pack2(g0.x, g1.x);  ve.y = pack2(g2.x, g3.x);
                vo.x = pack2(g0.y, g1.y);  vo.y = pack2(g2.y, g3.y);
                *(ulonglong2*)dst = ve;                      // timestep t
                *(ulonglong2*)(dst + (size_t)CB * 64) = vo;  // timestep t+1
            }
        }
        __syncthreads();
    }
}

// ---------------------------------------------------------------------------
// K2: recurrence. 4 warps/block, each warp owns 2 batches; lane j = unit j.
// Weights smem pre-paired: Wp[k*32+j] = {(wi,wf),(wg,wo)}  (1 LDS.128/k).
// h smem pre-duplicated per warp: hs[w][k] = {<h0,h0>,<h1,h1>} (1 bc LDS.128/k).
// Inner loop per k: 2 LDS.128 + 4 FFMA2. fc fused.
// ---------------------------------------------------------------------------
__device__ __forceinline__ float sigmf(float v) {
    return __fdividef(1.f, 1.f + __expf(-v));
}
__device__ __forceinline__ float tanhf_fast(float v) {
    return 1.f - __fdividef(2.f, 1.f + __expf(2.f * v));
}
__device__ __forceinline__ void lstm_cell(float gi, float gf, float gg, float go,
                                          float& c, float& h) {
    float iv = sigmf(gi);
    float fv = sigmf(gf);
    float gv = tanhf_fast(gg);
    float ov = sigmf(go);
    c = fv * c + iv * gv;
    h = ov * tanhf_fast(c);
}

#define K2W 4   // warps per block, 2 batches each

__global__ __launch_bounds__(32 * K2W) void k2_rnn(
    const float* __restrict__ Whh, const float* __restrict__ wfc,
    const float* __restrict__ bfc, float* __restrict__ out)
{
    __shared__ ulonglong2 Wp[CH * CH];      // 16 KB, shared by all warps
    __shared__ ulonglong2 hs[K2W][CH];      // per-warp dup'd h: {<h0,h0>,<h1,h1>}

    const int tid = threadIdx.x;
    const int j   = tid & 31;
    const int w   = tid >> 5;
    const int b0  = (blockIdx.x * K2W + w) * 2;

    // Stage paired weights: Wp[k*32+jj] = {(wi,wf),(wg,wo)} for unit jj
    for (int idx = tid; idx < CH * CH; idx += 32 * K2W) {
        int kk = idx >> 5, jj = idx & 31;
        ulonglong2 v;
        v.x = pack2(Whh[(0 * CH + jj) * CH + kk], Whh[(1 * CH + jj) * CH + kk]);
        v.y = pack2(Whh[(2 * CH + jj) * CH + kk], Whh[(3 * CH + jj) * CH + kk]);
        Wp[idx] = v;
    }
    {
        u64 z = pack2(0.f, 0.f);
        ulonglong2 zz; zz.x = z; zz.y = z;
        hs[w][j] = zz;
    }
    float c[2] = {0.f, 0.f};
    float h[2] = {0.f, 0.f};
    const float wfcv = wfc[j];
    __syncthreads();

    // xg pointers: ((t*CB + b0+bi)*32 + j)*2 u64
    const u64* xptr = g_xg + ((size_t)b0) * 64 + j * 2;
    const size_t TSTRIDE = (size_t)CB * 64;

    ulonglong2 xc[2];
    xc[0] = *(const ulonglong2*)(xptr);
    xc[1] = *(const ulonglong2*)(xptr + 64);
    xptr += TSTRIDE;

    for (int t = 0; t < CT; t++) {
        ulonglong2 xn[2];
        xn[0] = *(const ulonglong2*)(xptr);
        xn[1] = *(const ulonglong2*)(xptr + 64);
        xptr += TSTRIDE;

        u64 acc[2][2];
        acc[0][0] = xc[0].x;  acc[0][1] = xc[0].y;   // b0:   {i,f} {g,o}
        acc[1][0] = xc[1].x;  acc[1][1] = xc[1].y;   // b0+1

        #pragma unroll
        for (int k = 0; k < CH; k++) {
            const ulonglong2 wv = Wp[k * 32 + j];   // lane-distinct pairs
            const ulonglong2 hd = hs[w][k];         // broadcast {<h0,h0>,<h1,h1>}
            acc[0][0] = ffma2(hd.x, wv.x, acc[0][0]);
            acc[0][1] = ffma2(hd.x, wv.y, acc[0][1]);
            acc[1][0] = ffma2(hd.y, wv.x, acc[1][0]);
            acc[1][1] = ffma2(hd.y, wv.y, acc[1][1]);
        }
        __syncwarp();   // all lanes done reading hs(t)

        #pragma unroll
        for (int bi = 0; bi < 2; bi++) {
            float2 p0 = unpack2(acc[bi][0]);  // {i_pre, f_pre}
            float2 p1 = unpack2(acc[bi][1]);  // {g_pre, o_pre}
            lstm_cell(p0.x, p0.y, p1.x, p1.y, c[bi], h[bi]);
        }
        {
            ulonglong2 v;
            v.x = pack2(h[0], h[0]);
            v.y = pack2(h[1], h[1]);
            hs[w][j] = v;
        }
        __syncwarp();   // hs(t+1) visible

        xc[0] = xn[0];  xc[1] = xn[1];
    }

    // Fused fc: out[b] = sum_j h[b][j] * W_fc[0][j] + b_fc
    #pragma unroll
    for (int bi = 0; bi < 2; bi++) {
        float v = h[bi] * wfcv;
        #pragma unroll
        for (int off = 16; off > 0; off >>= 1)
            v += __shfl_xor_sync(0xffffffffu, v, off);
        if (j == 0) out[b0 + bi] = v + bfc[0];
    }
}

// ---------------------------------------------------------------------------
extern "C" void kernel_launch(void* const* d_in, const int* in_sizes, int n_in,
                              void* d_out, int out_size)
{
    const float* x   = (const float*)d_in[0];
    const float* Wih = (const float*)d_in[1];
    const float* Whh = (const float*)d_in[2];
    const float* bih = (const float*)d_in[3];
    const float* bhh = (const float*)d_in[4];
    const float* Wfc = (const float*)d_in[5];
    const float* bfc = (const float*)d_in[6];
    float* out = (float*)d_out;

    const int smem1 = 64 * WTS2 * 8 + 2 * 64 * XTS * 4;  // 66560 + 67584 = 134144 B
    cudaFuncSetAttribute(k1_inproj, cudaFuncAttributeMaxDynamicSharedMemorySize, smem1);

    const int g1 = (CB * CT) / (128 * K1T);   // 1024 blocks
    k1_inproj<<<g1, 256, smem1>>>(x, Wih, bih, bhh);
    k2_rnn<<<CB / (2 * K2W), 32 * K2W>>>(Whh, Wfc, bfc, out);
}

// round 6
// speedup vs baseline: 1.1811x; 1.1811x over previous
#include <cuda_runtime.h>

typedef unsigned long long u64;

#define CB  2048
#define CT  512
#define CI  64
#define CH  32
#define CG  128

// Scratch: g_xg[((t*CB + b)*32 + j)*2 + {0,1}] = {(xg_i,xg_f),(xg_g,xg_o)} for unit j.
// One extra timestep slab so K2's t+1 prefetch never reads OOB.
__device__ u64 g_xg[(size_t)(CT + 1) * CB * 64];

__device__ __forceinline__ u64 ffma2(u64 a, u64 b, u64 c) {
    u64 d;
    asm("fma.rn.f32x2 %0, %1, %2, %3;" : "=l"(d) : "l"(a), "l"(b), "l"(c));
    return d;
}
__device__ __forceinline__ u64 pack2(float lo, float hi) {
    u64 d;
    asm("mov.b64 %0, {%1, %2};" : "=l"(d) : "f"(lo), "f"(hi));
    return d;
}
__device__ __forceinline__ float2 unpack2(u64 v) {
    float2 r;
    asm("mov.b64 {%0, %1}, %2;" : "=f"(r.x), "=f"(r.y) : "l"(v));
    return r;
}

// ---------------------------------------------------------------------------
// K1: input projection as ONE flattened GEMM over rows m = b*CT + t.
//   out_row(m) = x_row(m) @ W_ih^T + bias      [1M x 64] x [64 x 128]
// Block: 256 thr, 8 tiles of 128 rows, W staged once (dup'd u64), x staged
// single-buffered with coalesced float4 loads. 100KB smem -> 2 blocks/SM.
// Thread tile: 2 j-cols x 4 gate-blocks x 8 rows (f32x2 over row pairs).
// ---------------------------------------------------------------------------
#define WTS2 130      // u64 stride for Wt2 rows
#define XTS  132      // float stride for xs rows (k index)
#define K1T  8        // row-tiles per block

extern __shared__ char sm1[];

__global__ __launch_bounds__(256, 2) void k1_inproj(
    const float* __restrict__ x, const float* __restrict__ Wih,
    const float* __restrict__ bih, const float* __restrict__ bhh)
{
    u64*   Wt2 = (u64*)sm1;                        // Wt2[k*WTS2 + g] = {w,w}
    float* xs  = (float*)(sm1 + 64 * WTS2 * 8);    // xs[k*XTS + r]
    const int tid = threadIdx.x;
    const size_t m0 = (size_t)blockIdx.x * (128 * K1T);

    // Stage W_ih duplicated (once per block)
    #pragma unroll
    for (int idx = tid; idx < CG * CI; idx += 256) {
        int g = idx >> 6, k = idx & 63;
        float w = Wih[idx];
        Wt2[k * WTS2 + g] = pack2(w, w);
    }

    const int tx = tid & 15, ty = tid >> 4;
    const int jj0 = tx * 2, r0 = ty * 8;
    const int mr = tid >> 4, kq = tid & 15;   // staging coords (row, float4-col)

    // Bias pairs
    u64 bd[2][4];
    #pragma unroll
    for (int q = 0; q < 2; q++)
        #pragma unroll
        for (int gb = 0; gb < 4; gb++) {
            int g = gb * 32 + jj0 + q;
            float bs = bih[g] + bhh[g];
            bd[q][gb] = pack2(bs, bs);
        }

    const float4* x4 = (const float4*)x;   // 16 float4 per row

    // Prologue: load tile 0
    float4 nxt[8];
    #pragma unroll
    for (int i = 0; i < 8; i++)
        nxt[i] = x4[(m0 + mr + i * 16) * 16 + kq];

    for (int tile = 0; tile < K1T; tile++) {
        const size_t mt = m0 + (size_t)tile * 128;

        __syncthreads();   // previous k-loop done with xs
        #pragma unroll
        for (int i = 0; i < 8; i++) {
            float* d = &xs[(4 * kq) * XTS + mr + i * 16];
            d[0 * XTS] = nxt[i].x;  d[1 * XTS] = nxt[i].y;
            d[2 * XTS] = nxt[i].z;  d[3 * XTS] = nxt[i].w;
        }
        __syncthreads();

        // Prefetch next tile (LDGs in flight under the k-loop)
        if (tile + 1 < K1T) {
            #pragma unroll
            for (int i = 0; i < 8; i++)
                nxt[i] = x4[(mt + 128 + mr + i * 16) * 16 + kq];
        }

        u64 acc[2][4][4];
        #pragma unroll
        for (int q = 0; q < 2; q++)
            #pragma unroll
            for (int gb = 0; gb < 4; gb++)
                #pragma unroll
                for (int p = 0; p < 4; p++) acc[q][gb][p] = bd[q][gb];

        #pragma unroll 4
        for (int k = 0; k < CI; k++) {
            const ulonglong2 xa = *(const ulonglong2*)&xs[k * XTS + r0];
            const ulonglong2 xb = *(const ulonglong2*)&xs[k * XTS + r0 + 4];
            u64 xp[4] = {xa.x, xa.y, xb.x, xb.y};
            const ulonglong2 w0 = *(const ulonglong2*)&Wt2[k * WTS2 +  0 + jj0];
            const ulonglong2 w1 = *(const ulonglong2*)&Wt2[k * WTS2 + 32 + jj0];
            const ulonglong2 w2 = *(const ulonglong2*)&Wt2[k * WTS2 + 64 + jj0];
            const ulonglong2 w3 = *(const ulonglong2*)&Wt2[k * WTS2 + 96 + jj0];
            #pragma unroll
            for (int p = 0; p < 4; p++) {
                acc[0][0][p] = ffma2(xp[p], w0.x, acc[0][0][p]);
                acc[0][1][p] = ffma2(xp[p], w1.x, acc[0][1][p]);
                acc[0][2][p] = ffma2(xp[p], w2.x, acc[0][2][p]);
                acc[0][3][p] = ffma2(xp[p], w3.x, acc[0][3][p]);
                acc[1][0][p] = ffma2(xp[p], w0.y, acc[1][0][p]);
                acc[1][1][p] = ffma2(xp[p], w1.y, acc[1][1][p]);
                acc[1][2][p] = ffma2(xp[p], w2.y, acc[1][2][p]);
                acc[1][3][p] = ffma2(xp[p], w3.y, acc[1][3][p]);
            }
        }

        // Store. Row pair (even m_e, odd m_e+1) = consecutive t, same b.
        #pragma unroll
        for (int p = 0; p < 4; p++) {
            const size_t m_e = mt + r0 + 2 * p;
            const int b = (int)(m_e >> 9);
            const int t = (int)(m_e & 511);
            #pragma unroll
            for (int q = 0; q < 2; q++) {
                float2 g0 = unpack2(acc[q][0][p]);
                float2 g1 = unpack2(acc[q][1][p]);
                float2 g2 = unpack2(acc[q][2][p]);
                float2 g3 = unpack2(acc[q][3][p]);
                u64* dst = g_xg + ((size_t)t * CB + b) * 64 + (jj0 + q) * 2;
                ulonglong2 ve, vo;
                ve.x = pack2(g0.x, g1.x);  ve.y = pack2(g2.x, g3.x);
                vo.x = pack2(g0.y, g1.y);  vo.y = pack2(g2.y, g3.y);
                *(ulonglong2*)dst = ve;                      // timestep t
                *(ulonglong2*)(dst + (size_t)CB * 64) = vo;  // timestep t+1
            }
        }
    }
}

// ---------------------------------------------------------------------------
// K2: recurrence, NO smem in the loop. Each warp owns 2 batches; lane j =
// hidden unit j. W_hh register-resident as gate-pairs (64 u64). h exchanged
// via __shfl_sync (implicit warp sync). Inner loop per k: 2 SHFL + 2 pack +
// 4 FFMA2. fc fused at the end.
// ---------------------------------------------------------------------------
__device__ __forceinline__ float sigmf(float v) {
    return __fdividef(1.f, 1.f + __expf(-v));
}
__device__ __forceinline__ float tanhf_fast(float v) {
    return 1.f - __fdividef(2.f, 1.f + __expf(2.f * v));
}
__device__ __forceinline__ void lstm_cell(float gi, float gf, float gg, float go,
                                          float& c, float& h) {
    float iv = sigmf(gi);
    float fv = sigmf(gf);
    float gv = tanhf_fast(gg);
    float ov = sigmf(go);
    c = fv * c + iv * gv;
    h = ov * tanhf_fast(c);
}

#define K2W 2   // warps per block

__global__ __launch_bounds__(32 * K2W) void k2_rnn(
    const float* __restrict__ Whh, const float* __restrict__ wfc,
    const float* __restrict__ bfc, float* __restrict__ out)
{
    const int tid = threadIdx.x;
    const int j   = tid & 31;
    const int gw  = blockIdx.x * K2W + (tid >> 5);
    const int b0  = gw * 2;

    // Register-resident recurrent weights, gate-paired per unit j:
    // wif[k] = {W_hh[i_j][k], W_hh[f_j][k]},  wgo[k] = {W_hh[g_j][k], W_hh[o_j][k]}
    u64 wif[CH], wgo[CH];
    #pragma unroll
    for (int k = 0; k < CH; k++) {
        wif[k] = pack2(__ldg(&Whh[(0 * CH + j) * CH + k]),
                       __ldg(&Whh[(1 * CH + j) * CH + k]));
        wgo[k] = pack2(__ldg(&Whh[(2 * CH + j) * CH + k]),
                       __ldg(&Whh[(3 * CH + j) * CH + k]));
    }

    float h0 = 0.f, h1 = 0.f, c0 = 0.f, c1 = 0.f;
    const float wfcv = wfc[j];

    // xg pointers: ((t*CB + b0+bi)*32 + j)*2 u64
    const u64* xptr = g_xg + ((size_t)b0) * 64 + j * 2;
    const size_t TSTRIDE = (size_t)CB * 64;

    ulonglong2 xc0 = *(const ulonglong2*)(xptr);
    ulonglong2 xc1 = *(const ulonglong2*)(xptr + 64);
    xptr += TSTRIDE;

    for (int t = 0; t < CT; t++) {
        ulonglong2 xn0 = *(const ulonglong2*)(xptr);
        ulonglong2 xn1 = *(const ulonglong2*)(xptr + 64);
        xptr += TSTRIDE;

        u64 a0_if = xc0.x, a0_go = xc0.y;
        u64 a1_if = xc1.x, a1_go = xc1.y;

        #pragma unroll
        for (int k = 0; k < CH; k++) {
            float v0 = __shfl_sync(0xffffffffu, h0, k);
            float v1 = __shfl_sync(0xffffffffu, h1, k);
            u64 d0 = pack2(v0, v0);
            u64 d1 = pack2(v1, v1);
            a0_if = ffma2(d0, wif[k], a0_if);
            a0_go = ffma2(d0, wgo[k], a0_go);
            a1_if = ffma2(d1, wif[k], a1_if);
            a1_go = ffma2(d1, wgo[k], a1_go);
        }

        float2 p0 = unpack2(a0_if);   // {i, f}
        float2 p1 = unpack2(a0_go);   // {g, o}
        lstm_cell(p0.x, p0.y, p1.x, p1.y, c0, h0);
        float2 q0 = unpack2(a1_if);
        float2 q1 = unpack2(a1_go);
        lstm_cell(q0.x, q0.y, q1.x, q1.y, c1, h1);

        xc0 = xn0;  xc1 = xn1;
    }

    // Fused fc: out[b] = sum_j h[b][j] * W_fc[0][j] + b_fc
    float v0 = h0 * wfcv;
    float v1 = h1 * wfcv;
    #pragma unroll
    for (int off = 16; off > 0; off >>= 1) {
        v0 += __shfl_xor_sync(0xffffffffu, v0, off);
        v1 += __shfl_xor_sync(0xffffffffu, v1, off);
    }
    if (j == 0) {
        float bb = bfc[0];
        out[b0]     = v0 + bb;
        out[b0 + 1] = v1 + bb;
    }
}

// ---------------------------------------------------------------------------
extern "C" void kernel_launch(void* const* d_in, const int* in_sizes, int n_in,
                              void* d_out, int out_size)
{
    const float* x   = (const float*)d_in[0];
    const float* Wih = (const float*)d_in[1];
    const float* Whh = (const float*)d_in[2];
    const float* bih = (const float*)d_in[3];
    const float* bhh = (const float*)d_in[4];
    const float* Wfc = (const float*)d_in[5];
    const float* bfc = (const float*)d_in[6];
    float* out = (float*)d_out;

    const int smem1 = 64 * WTS2 * 8 + 64 * XTS * 4;  // 66560 + 33792 = 100352 B
    cudaFuncSetAttribute(k1_inproj, cudaFuncAttributeMaxDynamicSharedMemorySize, smem1);

    const int g1 = (CB * CT) / (128 * K1T);   // 1024 blocks
    k1_inproj<<<g1, 256, smem1>>>(x, Wih, bih, bhh);
    k2_rnn<<<CB / (2 * K2W), 32 * K2W>>>(Whh, Wfc, bfc, out);
}